// round 12
// baseline (speedup 1.0000x reference)
#include <cuda_runtime.h>
#include <cstdint>

// Problem constants (fixed by the reference)
#define BB 2
#define LL 1024
#define MM 8
#define NN 16
#define CC 16
#define HH 64
#define WW 64
#define VOTES (MM * NN)            // 128
#define SLAB  (CC * HH * WW)       // 65536 floats = 256 KB per (b,l)
#define CGRP  4                    // channels per quantum (R10 had 2)
#define NGRP  (CC / CGRP)          // 4 quanta per slab
#define PLANE (HH * WW)            // 4096
#define QFLOATS (CGRP * PLANE)     // 16384 floats = 64 KB per quantum

// Matrix completion: CGRP=4 quantum with R10's direct-register tail.
// One CTA (256 threads) = one 64 KB quantum: threads 0-127 gather one vote
// (4 channels, float4) -> all 256 threads stream-zero 64 KB (16 STG.128
// each) -> __syncthreads -> vote threads issue 4 atomicAdds from registers;
// threads 128-255 retire at the barrier. Halves gather duplication and
// barrier count vs R10 (CGRP=2) at slightly coarser tail quantization.
__global__ __launch_bounds__(256, 8)
void ht_vote_kernel(const float* __restrict__ feats,   // [B,L,N,C]
                    const int*   __restrict__ vsrc,    // [B,L,2]
                    const int*   __restrict__ vdst,    // [B,L,2]
                    const int*   __restrict__ isrc,    // [B,L,M]
                    const int*   __restrict__ idst,    // [B,L,N]
                    float* __restrict__ out)           // [B,L,C,H,W]
{
    const int q  = blockIdx.x;         // 0 .. B*L*NGRP-1
    const int bl = q >> 2;             // NGRP == 4
    const int g  = q & 3;              // channel group
    const int b  = bl >> 10;           // LL == 1024
    const int t  = threadIdx.x;

    // ---- Gather chain: issued before the store stream; the ~3 dependent
    // L2 latencies hide under the 64 KB of independent stores.
    int    bin = -1;
    float4 w   = make_float4(0.f, 0.f, 0.f, 0.f);
    if (t < VOTES) {
        const int m = t >> 4;          // NN == 16
        const int n = t & 15;

        const int s  = isrc[bl * MM + m];
        const int d  = idst[(b * LL + s) * NN + n];
        const int sy = vsrc[(b * LL + s) * 2 + 0];
        const int sx = vsrc[(b * LL + s) * 2 + 1];
        const int dy = vdst[(b * LL + d) * 2 + 0];
        const int dx = vdst[(b * LL + d) * 2 + 1];

        // voxels are int32: floor(float sub) == integer sub exactly
        const int by = dy - sy + HH / 2;
        const int bx = dx - sx + WW / 2;
        if (((unsigned)by < HH) & ((unsigned)bx < WW)) bin = by * WW + bx;

        // 4 channels of this vote's weights (16B, coalesced, L2-hot)
        w = ((const float4*)(feats + (((size_t)(b * LL + s)) * NN + n) * CC))[g];
    }

    float* base = out + (size_t)bl * SLAB + g * QFLOATS;

    // ---- Stream-zero this quantum's 64 KB (16 float4 per thread) ----
    {
        float4* b4 = (float4*)base;
        const float4 z = make_float4(0.f, 0.f, 0.f, 0.f);
#pragma unroll
        for (int i = 0; i < QFLOATS / 4 / 256; i++)
            b4[t + i * 256] = z;
    }

    __syncthreads();   // all zero-stores of this CTA-private quantum complete
                       // & visible before any scattered atomic touches it

    // ---- Scatter: vote threads commit 4 channels from registers (REDG) ----
    if (bin >= 0) {
        atomicAdd(base             + bin, w.x);
        atomicAdd(base + 1 * PLANE + bin, w.y);
        atomicAdd(base + 2 * PLANE + bin, w.z);
        atomicAdd(base + 3 * PLANE + bin, w.w);
    }
}

extern "C" void kernel_launch(void* const* d_in, const int* in_sizes, int n_in,
                              void* d_out, int out_size)
{
    const float* feats = (const float*)d_in[0];   // [B,L,N,C] f32
    const int*   vsrc  = (const int*)  d_in[1];   // [B,L,2]   i32
    const int*   vdst  = (const int*)  d_in[2];   // [B,L,2]   i32
    const int*   isrc  = (const int*)  d_in[3];   // [B,L,M]   i32
    const int*   idst  = (const int*)  d_in[4];   // [B,L,N]   i32
    float*       out   = (float*)d_out;           // [B,L,C,H,W] f32

    ht_vote_kernel<<<BB * LL * NGRP, 256>>>(feats, vsrc, vdst, isrc, idst, out);
}

// round 13
// speedup vs baseline: 1.0312x; 1.0312x over previous
#include <cuda_runtime.h>
#include <cstdint>

// Problem constants (fixed by the reference)
#define BB 2
#define LL 1024
#define MM 8
#define NN 16
#define CC 16
#define HH 64
#define WW 64
#define VOTES (MM * NN)            // 128
#define SLAB  (CC * HH * WW)       // 65536 floats = 256 KB per (b,l)
#define CGRP  2                    // channels per quantum (measured optimum)
#define NGRP  (CC / CGRP)          // 8 quanta per slab
#define PLANE (HH * WW)            // 4096
#define QFLOATS (CGRP * PLANE)     // 8192 floats = 32 KB per quantum

// R10 champion with the tail spread to 1 atomic per thread:
// ALL 256 threads run the gather chain for vote (t & 127) — duplication is
// L2-resident noise, fully hidden under the store stream — and after the
// barrier each thread commits exactly ONE channel:
//   threads   0-127 -> channel 0 of vote t
//   threads 128-255 -> channel 1 of vote t-128
// This halves the per-thread serialized REDG tail vs R10 (2 atomics on one
// half-block) with identical barrier count and store stream.
__global__ __launch_bounds__(256, 8)
void ht_vote_kernel(const float* __restrict__ feats,   // [B,L,N,C]
                    const int*   __restrict__ vsrc,    // [B,L,2]
                    const int*   __restrict__ vdst,    // [B,L,2]
                    const int*   __restrict__ isrc,    // [B,L,M]
                    const int*   __restrict__ idst,    // [B,L,N]
                    float* __restrict__ out)           // [B,L,C,H,W]
{
    const int q  = blockIdx.x;         // 0 .. B*L*NGRP-1
    const int bl = q >> 3;             // NGRP == 8
    const int g  = q & 7;              // channel group
    const int b  = bl >> 10;           // LL == 1024
    const int t  = threadIdx.x;
    const int v  = t & 127;            // vote id (each vote handled twice)
    const int c  = t >> 7;             // channel within group (0 or 1)

    // ---- Gather chain (all threads): issued before the store stream; the
    // ~3 dependent L2 latencies hide under the 32 KB of independent stores.
    const int m = v >> 4;              // NN == 16
    const int n = v & 15;

    const int s  = isrc[bl * MM + m];
    const int d  = idst[(b * LL + s) * NN + n];
    const int sy = vsrc[(b * LL + s) * 2 + 0];
    const int sx = vsrc[(b * LL + s) * 2 + 1];
    const int dy = vdst[(b * LL + d) * 2 + 0];
    const int dx = vdst[(b * LL + d) * 2 + 1];

    // voxels are int32: floor(float sub) == integer sub exactly
    const int by = dy - sy + HH / 2;
    const int bx = dx - sx + WW / 2;
    int bin = -1;
    if (((unsigned)by < HH) & ((unsigned)bx < WW)) bin = by * WW + bx;

    // this thread's single channel weight (scalar LDG, L2-hot)
    const float w = feats[(((size_t)(b * LL + s)) * NN + n) * CC + g * CGRP + c];

    float* base = out + (size_t)bl * SLAB + g * QFLOATS;

    // ---- Stream-zero this quantum's 32 KB (8 float4 per thread) ----
    {
        float4* b4 = (float4*)base;
        const float4 z = make_float4(0.f, 0.f, 0.f, 0.f);
#pragma unroll
        for (int i = 0; i < QFLOATS / 4 / 256; i++)
            b4[t + i * 256] = z;
    }

    __syncthreads();   // all zero-stores of this CTA-private quantum complete
                       // & visible before any scattered atomic touches it

    // ---- Scatter: exactly one atomicAdd per thread (REDG, L2-hot) ----
    if (bin >= 0)
        atomicAdd(base + c * PLANE + bin, w);
}

extern "C" void kernel_launch(void* const* d_in, const int* in_sizes, int n_in,
                              void* d_out, int out_size)
{
    const float* feats = (const float*)d_in[0];   // [B,L,N,C] f32
    const int*   vsrc  = (const int*)  d_in[1];   // [B,L,2]   i32
    const int*   vdst  = (const int*)  d_in[2];   // [B,L,2]   i32
    const int*   isrc  = (const int*)  d_in[3];   // [B,L,M]   i32
    const int*   idst  = (const int*)  d_in[4];   // [B,L,N]   i32
    float*       out   = (float*)d_out;           // [B,L,C,H,W] f32

    ht_vote_kernel<<<BB * LL * NGRP, 256>>>(feats, vsrc, vdst, isrc, idst, out);
}